// round 17
// baseline (speedup 1.0000x reference)
#include <cuda_runtime.h>

#define TPB 128
#define XPAD 62   // per-problem smem stride (even -> 8B-aligned LDS.64; 2-way conflicts max)

typedef unsigned long long ull;

__device__ __forceinline__ ull pk(float lo, float hi) {
    ull r; asm("mov.b64 %0, {%1, %2};" : "=l"(r) : "f"(lo), "f"(hi)); return r;
}
__device__ __forceinline__ float lo2(ull v) { return __uint_as_float((unsigned)v); }
__device__ __forceinline__ float hi2(ull v) { return __uint_as_float((unsigned)(v >> 32)); }
__device__ __forceinline__ ull fma2(ull a, ull b, ull c) {
    ull d; asm("fma.rn.f32x2 %0, %1, %2, %3;" : "=l"(d) : "l"(a), "l"(b), "l"(c)); return d;
}
__device__ __forceinline__ ull mul2(ull a, ull b) {
    ull d; asm("mul.rn.f32x2 %0, %1, %2;" : "=l"(d) : "l"(a), "l"(b)); return d;
}
__device__ __forceinline__ ull add2(ull a, ull b) {
    ull d; asm("add.rn.f32x2 %0, %1, %2;" : "=l"(d) : "l"(a), "l"(b)); return d;
}
__device__ __forceinline__ float ex2(float x) {
    float r; asm("ex2.approx.f32 %0, %1;" : "=f"(r) : "f"(x)); return r;
}

// One thread = one batch problem. Transposed smem: x[j][d] at d*10+j.
// Phase 2: SOFTWARE-PIPELINED single-query loop. Iteration i fires 10 ex2 for
// query i, then computes the NEXT query's 5 independent score chains (60+ issue
// cycles of fma2) to bury the ex2 latency, then packs/accumulates/divides query i.
// S'_ij = (x_i^T M x_j + r.x_j)*log2(e); out_i = sum 2^s vsum / sum 2^s.
// smem constants (dup-packed float2): [0..35] M*L2E, [36..41] r*L2E, [42..47] wv, [48] cv
__global__ __launch_bounds__(TPB, 3) void attn_kernel(
    const float* __restrict__ x,
    const float* __restrict__ Wk, const float* __restrict__ bk,
    const float* __restrict__ Wq, const float* __restrict__ bq,
    const float* __restrict__ Wv, const float* __restrict__ bv,
    float* __restrict__ out)
{
    __shared__ float2 cst[49];
    __shared__ float  xs[TPB * XPAD];
    const int t = threadIdx.x;

    // ---- per-block precompute of dup-packed constants ----
    if (t < 49) {
        const float L2E = 1.4426950408889634f;
        float s = 0.f;
        if (t < 36) {                    // M[a][b] = sum_e Wq[e][a] Wk[e][b]  (*L2E)
            int a = t / 6, b = t % 6;
            #pragma unroll
            for (int e = 0; e < 6; e++) s += Wq[e*6 + a] * Wk[e*6 + b];
            s *= L2E;
        } else if (t < 42) {             // r[b] = sum_e bq[e] Wk[e][b]  (*L2E)
            int b = t - 36;
            #pragma unroll
            for (int e = 0; e < 6; e++) s += bq[e] * Wk[e*6 + b];
            s *= L2E;
        } else if (t < 48) {             // wv[d] = colsum(Wv)
            int d = t - 42;
            #pragma unroll
            for (int e = 0; e < 6; e++) s += Wv[e*6 + d];
        } else {                         // cv = sum(bv)
            #pragma unroll
            for (int e = 0; e < 6; e++) s += bv[e];
        }
        cst[t] = make_float2(s, s);
    }

    // ---- staging (threads 0..119): 16 float4 each, loop-invariant transpose addressing ----
    if (t < 120) {
        const float4* xg = (const float4*)(x + (size_t)blockIdx.x * (TPB * 60)) + t;
        int tb = (4 * t) / 60;
        int te = 4 * t - 60 * tb;
        int j0 = te / 6, d0 = te - 6 * j0;
        int ro = (d0 == 4) ? 59 : 0;
        int a0 = tb * XPAD + d0 * 10 + j0;
        #pragma unroll
        for (int i = 0; i < 16; i++) {
            float4 v = xg[i * 120];
            xs[a0]           = v.x;
            xs[a0 + 10]      = v.y;
            xs[a0 + 20 - ro] = v.z;
            xs[a0 + 30 - ro] = v.w;
            a0 += 8 * XPAD;
        }
    }
    __syncthreads();

    const float* xp = &xs[t * XPAD];
    const ull*   XX = (const ull*)xp;               // XX[d*5 + m] = (x[2m][d], x[2m+1][d])
    const ull*   C  = reinterpret_cast<const ull*>(cst);

    // ---- phase 1, d-outer, fully packed ----
    ull G[6][5], hp[5], vp[5];
    {   // d = 0
        ull xx0 = XX[0], xx1 = XX[1], xx2 = XX[2], xx3 = XX[3], xx4 = XX[4];
        #pragma unroll
        for (int a = 0; a < 6; a++) {
            ull m = C[a*6];
            G[a][0] = mul2(m, xx0); G[a][1] = mul2(m, xx1); G[a][2] = mul2(m, xx2);
            G[a][3] = mul2(m, xx3); G[a][4] = mul2(m, xx4);
        }
        ull r = C[36], w = C[42], cv = C[48];
        hp[0] = mul2(r, xx0); hp[1] = mul2(r, xx1); hp[2] = mul2(r, xx2);
        hp[3] = mul2(r, xx3); hp[4] = mul2(r, xx4);
        vp[0] = fma2(w, xx0, cv); vp[1] = fma2(w, xx1, cv); vp[2] = fma2(w, xx2, cv);
        vp[3] = fma2(w, xx3, cv); vp[4] = fma2(w, xx4, cv);
    }
    #pragma unroll
    for (int d = 1; d < 6; d++) {
        ull xx[5];
        #pragma unroll
        for (int jp = 0; jp < 5; jp++) xx[jp] = XX[d*5 + jp];
        #pragma unroll
        for (int a = 0; a < 6; a++) {
            ull m = C[a*6 + d];
            #pragma unroll
            for (int jp = 0; jp < 5; jp++) G[a][jp] = fma2(m, xx[jp], G[a][jp]);
        }
        ull r = C[36 + d], w = C[42 + d];
        #pragma unroll
        for (int jp = 0; jp < 5; jp++) {
            hp[jp] = fma2(r, xx[jp], hp[jp]);
            vp[jp] = fma2(w, xx[jp], vp[jp]);
        }
    }

    // ---- phase 2: software-pipelined over 10 queries ----
    float res[10];
    ull X[6], s[5];
    #pragma unroll
    for (int a = 0; a < 6; a++) { float xv = xp[a*10 + 0]; X[a] = pk(xv, xv); }
    #pragma unroll
    for (int jp = 0; jp < 5; jp++) {
        ull v = fma2(X[0], G[0][jp], hp[jp]);
        #pragma unroll
        for (int a = 1; a < 6; a++) v = fma2(X[a], G[a][jp], v);
        s[jp] = v;
    }

    #pragma unroll
    for (int i = 0; i < 10; i++) {
        // (1) fire 10 ex2 for query i
        float f[10];
        #pragma unroll
        for (int jp = 0; jp < 5; jp++) {
            f[2*jp]     = ex2(lo2(s[jp]));
            f[2*jp + 1] = ex2(hi2(s[jp]));
        }

        // (2) latency shield: next query's 5 independent score chains
        ull ns[5];
        if (i < 9) {
            #pragma unroll
            for (int a = 0; a < 6; a++) { float xv = xp[a*10 + i + 1]; X[a] = pk(xv, xv); }
            #pragma unroll
            for (int jp = 0; jp < 5; jp++) {
                ull v = fma2(X[0], G[0][jp], hp[jp]);
                #pragma unroll
                for (int a = 1; a < 6; a++) v = fma2(X[a], G[a][jp], v);
                ns[jp] = v;
            }
        }

        // (3) pack + packed accumulate + divide for query i
        ull e0 = pk(f[0], f[1]);
        ull num = mul2(e0, vp[0]), den = e0;
        #pragma unroll
        for (int jp = 1; jp < 5; jp++) {
            ull e = pk(f[2*jp], f[2*jp + 1]);
            num = fma2(e, vp[jp], num);
            den = add2(den, e);
        }
        res[i] = __fdividef(lo2(num) + hi2(num), lo2(den) + hi2(den));

        if (i < 9) {
            #pragma unroll
            for (int jp = 0; jp < 5; jp++) s[jp] = ns[jp];
        }
    }

    // ---- output: 5 x float2 per thread ----
    float2* op = (float2*)(out + (size_t)(blockIdx.x * TPB + t) * 10);
    #pragma unroll
    for (int p = 0; p < 5; p++) op[p] = make_float2(res[2*p], res[2*p + 1]);
}

extern "C" void kernel_launch(void* const* d_in, const int* in_sizes, int n_in,
                              void* d_out, int out_size) {
    const float* x  = (const float*)d_in[0];
    const float* Wk = (const float*)d_in[1];
    const float* bk = (const float*)d_in[2];
    const float* Wq = (const float*)d_in[3];
    const float* bq = (const float*)d_in[4];
    const float* Wv = (const float*)d_in[5];
    const float* bv = (const float*)d_in[6];
    int B = in_sizes[0] / 60;            // 524288
    int blocks = B / TPB;                // 4096
    attn_kernel<<<blocks, TPB>>>(x, Wk, bk, Wq, bq, Wv, bv, (float*)d_out);
}